// round 13
// baseline (speedup 1.0000x reference)
#include <cuda_runtime.h>
#include <math.h>

typedef unsigned long long ull;

#define IMG 512
#define CHR 64      // output rows per chunk
#define BWC 288     // threads per block (2 strips x ~260 useful cols = 512)

__device__ double g_acc;

__global__ void init_acc_kernel() { g_acc = 0.0; }

__global__ void finalize_kernel(float* out, double scale) {
    out[0] = (float)(g_acc * scale);
}

// ---- f32x2 packed helpers ----
__device__ __forceinline__ ull pack2(float lo, float hi) {
    ull r;
    asm("mov.b64 %0, {%1, %2};" : "=l"(r) : "f"(lo), "f"(hi));
    return r;
}
__device__ __forceinline__ void unpack2(ull v, float& lo, float& hi) {
    asm("mov.b64 {%0, %1}, %2;" : "=f"(lo), "=f"(hi) : "l"(v));
}
__device__ __forceinline__ void ffma2(ull& d, ull a, ull b) {
    asm("fma.rn.f32x2 %0, %1, %2, %0;" : "+l"(d) : "l"(a), "l"(b));
}
__device__ __forceinline__ ull fma2v(ull a, ull b, ull c) {   // a*b + c
    ull d;
    asm("fma.rn.f32x2 %0, %1, %2, %3;" : "=l"(d) : "l"(a), "l"(b), "l"(c));
    return d;
}
__device__ __forceinline__ ull mul2(ull a, ull b) {
    ull d;
    asm("mul.rn.f32x2 %0, %1, %2;" : "=l"(d) : "l"(a), "l"(b));
    return d;
}
__device__ __forceinline__ ull add2(ull a, ull b) {
    ull d;
    asm("add.rn.f32x2 %0, %1, %2;" : "=l"(d) : "l"(a), "l"(b));
    return d;
}

// Batched streaming register-systolic pipeline. One thread = one column.
// U = R+1 rows per __syncthreads, double-buffered phase row rings.
// Lags (row-iteration units p): mean/S2 complete row p-R; xc[p-R] -> next
// phase buffer; hc3/hc4 convolve xc row p-U-R; m3/m4 complete row p-U-2R.
template <int K, int BW, int MINB, int CH>
__global__ __launch_bounds__(BW, MINB)
void stat_stream_kernel(const float* __restrict__ pred,
                        const float* __restrict__ tgt)
{
    constexpr int R    = K / 2;
    constexpr int U    = R + 1;           // rows per batch
    constexpr int D    = 2 * U;           // var-ring depth (2 phases)
    constexpr int H1N  = K / 2 + 1;       // taps in first half-chain
    constexpr int UWB  = BW - 4 * R;      // useful output columns per block
    constexpr int NRAW = CH + 4 * R + U;  // row-iterations needed
    constexpr int NB2  = (NRAW + D - 1) / D;   // batch PAIRS

    // smem: pad(8) | xc0 | x0 | xc1 | x1 | pad(8)   each U*BW u64
    __shared__ __align__(16) ull sbuf[4 * U * BW + 16];
    __shared__ float wsum[BW / 32];
    ull* const xc0 = sbuf + 8;
    ull* const xb0 = xc0 + U * BW;
    ull* const xc1 = xb0 + U * BW;
    ull* const xb1 = xc1 + U * BW;

    const int tid = threadIdx.x;
    const int c0  = blockIdx.y * CH;
    const int col = blockIdx.x * UWB - 2 * R + tid;
    const bool incol = (unsigned)col < (unsigned)IMG;
    const bool uc = (tid >= 2 * R) && (tid < 2 * R + UWB) && incol;
    const size_t plane = (size_t)blockIdx.z * (size_t)(IMG * IMG);

    // normalized 1D gaussian, packed into both lanes
    ull gp[K];
    {
        const float sigma = (float)K / 6.0f;
        const float inv2s2 = 1.0f / (2.0f * sigma * sigma);
        float gt[K];
        float s = 0.0f;
#pragma unroll
        for (int j = 0; j < K; ++j) {
            float c = (float)(j - K / 2);
            gt[j] = expf(-c * c * inv2s2);
            s += gt[j];
        }
        float inv = 1.0f / s;
#pragma unroll
        for (int j = 0; j < K; ++j) { float w = gt[j] * inv; gp[j] = pack2(w, w); }
    }
    const ull NEG1 = pack2(-1.0f, -1.0f);

    // systolic partials + packed variance ring
    ull Am[K - 1], As[K - 1], A3[K - 1], A4[K - 1];
#pragma unroll
    for (int i = 0; i < K - 1; ++i) { Am[i] = 0; As[i] = 0; A3[i] = 0; A4[i] = 0; }
    ull vr[D];
#pragma unroll
    for (int i = 0; i < D; ++i) vr[i] = 0;

    const int r0 = c0 - 2 * R;
    const float* pp = pred + plane + (long long)r0 * IMG + col;
    const float* pt = tgt  + plane + (long long)r0 * IMG + col;

    // preamble: fill x phase-0 rows r0..r0+U-1; zero everything else
#pragma unroll
    for (int u = 0; u < U; ++u) {
        int rr = r0 + u;
        float a = 0.0f, b = 0.0f;
        if (incol && ((unsigned)rr < (unsigned)IMG)) { a = pp[0]; b = pt[0]; }
        xb0[u * BW + tid] = pack2(a, b);
        xc0[u * BW + tid] = 0ull;
        xb1[u * BW + tid] = 0ull;
        xc1[u * BW + tid] = 0ull;
        pp += IMG; pt += IMG;
    }
    if (tid < 8) { sbuf[tid] = 0ull; sbuf[4 * U * BW + 8 + tid] = 0ull; }

    float acc = 0.0f;

#pragma unroll 1
    for (int bp = 0; bp < NB2; ++bp) {
#pragma unroll
        for (int ph = 0; ph < 2; ++ph) {
            const int p0 = (bp * 2 + ph) * U;
            ull* const xbC = ph ? xb1 : xb0;   // current-phase buffers (read)
            ull* const xcC = ph ? xc1 : xc0;
            ull* const xbN = ph ? xb0 : xb1;   // next-phase buffers (write)
            ull* const xcN = ph ? xc0 : xc1;

            __syncthreads();   // publishes of previous batch complete

#pragma unroll
            for (int u = 0; u < U; ++u) {
                const int p = p0 + u;

                // prefetch x row p+U straight into next phase's buffer
                {
                    int rr = r0 + p + U;
                    float a = 0.0f, b = 0.0f;
                    if (incol && ((unsigned)rr < (unsigned)IMG)) { a = pp[0]; b = pt[0]; }
                    xbN[u * BW + tid] = pack2(a, b);
                    pp += IMG; pt += IMG;
                }

                // ---- level-1 horizontal convs on x row p (2 half-chains) ----
                ull h1, hs2;
                {
                    const ull* xb = xbC + u * BW + (tid - R);
                    ull h1a = 0, h1b = 0, sa = 0, sb = 0;
#pragma unroll
                    for (int j = 0; j < K; ++j) {
                        ull t = xb[j];
                        ull t2 = mul2(t, t);
                        if (j < H1N) { ffma2(h1a, gp[j], t); ffma2(sa, gp[j], t2); }
                        else         { ffma2(h1b, gp[j], t); ffma2(sb, gp[j], t2); }
                    }
                    h1  = add2(h1a, h1b);
                    hs2 = add2(sa, sb);
                }

                // ---- mean/S2 vertical systolic: completes row p-R ----
                ull meanc = Am[0]; ffma2(meanc, gp[K - 1], h1);
                ull S2c   = As[0]; ffma2(S2c,   gp[K - 1], hs2);
#pragma unroll
                for (int i = 0; i < K - 2; ++i) {
                    ull a = Am[i + 1]; ffma2(a, gp[K - 2 - i], h1);  Am[i] = a;
                    ull b = As[i + 1]; ffma2(b, gp[K - 2 - i], hs2); As[i] = b;
                }
                Am[K - 2] = mul2(gp[0], h1);
                As[K - 2] = mul2(gp[0], hs2);

                // ---- xc at row p-R -> next phase's xc buffer ----
                {
                    // x row p-R, own column; u<R -> older phase content of xbN
                    ull xm = (u < R) ? xbN[(U - R + u) * BW + tid]
                                     : xbC[(u - R) * BW + tid];
                    int m_row = r0 + p - R;
                    bool mimg = incol && ((unsigned)m_row < (unsigned)IMG);
                    ull xcv = fma2v(meanc, NEG1, xm);
                    xcN[u * BW + tid] = mimg ? xcv : 0ull;
                }

                // ---- features at row p-R: |dmean|+|dvar|, store packed var ----
                {
                    const int m_idx = p - 3 * R;
                    if ((unsigned)m_idx < (unsigned)CH) {
                        float mp, mt, sp, st;
                        unpack2(meanc, mp, mt);
                        unpack2(S2c,   sp, st);
                        float vp = fmaxf(fmaf(-mp, mp, sp), 1e-8f);
                        float vt = fmaxf(fmaf(-mt, mt, st), 1e-8f);
                        if (uc) acc += fabsf(mp - mt) + fabsf(vp - vt);
                        vr[ph * U + u] = pack2(vp, vt);
                    }
                }

                // ---- level-2 horizontal convs on xc row p-U-R (2 half-chains) ----
                ull hc3, hc4;
                {
                    const ull* cb = xcC + u * BW + (tid - R);
                    ull c3a = 0, c3b = 0, c4a = 0, c4b = 0;
#pragma unroll
                    for (int j = 0; j < K; ++j) {
                        ull s  = cb[j];
                        ull s2 = mul2(s, s);
                        ull c3 = mul2(s2, s);
                        ull c4 = mul2(s2, s2);
                        if (j < H1N) { ffma2(c3a, gp[j], c3); ffma2(c4a, gp[j], c4); }
                        else         { ffma2(c3b, gp[j], c3); ffma2(c4b, gp[j], c4); }
                    }
                    hc3 = add2(c3a, c3b);
                    hc4 = add2(c4a, c4b);
                }

                // ---- m3/m4 vertical systolic: completes output row p-U-2R ----
                ull m3c = A3[0]; ffma2(m3c, gp[K - 1], hc3);
                ull m4c = A4[0]; ffma2(m4c, gp[K - 1], hc4);
#pragma unroll
                for (int i = 0; i < K - 2; ++i) {
                    ull a = A3[i + 1]; ffma2(a, gp[K - 2 - i], hc3); A3[i] = a;
                    ull b = A4[i + 1]; ffma2(b, gp[K - 2 - i], hc4); A4[i] = b;
                }
                A3[K - 2] = mul2(gp[0], hc3);
                A4[K - 2] = mul2(gp[0], hc4);

                {
                    const int o_idx = p - U - 4 * R;
                    if (((unsigned)o_idx < (unsigned)CH) && uc) {
                        const int slot = (ph * U + u + U - R) % D;  // var of this row
                        float vp, vt;
                        unpack2(vr[slot], vp, vt);
                        float m3p, m3t, m4p, m4t;
                        unpack2(m3c, m3p, m3t);
                        unpack2(m4c, m4p, m4t);
                        float sdp = sqrtf(vp), sdt = sqrtf(vt);
                        float skp = __fdividef(m3p, fmaf(sdp, vp, 1e-8f));
                        float skt = __fdividef(m3t, fmaf(sdt, vt, 1e-8f));
                        float kup = __fdividef(m4p, fmaf(vp, vp, 1e-8f));
                        float kut = __fdividef(m4t, fmaf(vt, vt, 1e-8f));
                        acc += 0.5f   * fabsf(skp - skt)
                             + 0.001f * fabsf(kup - kut);
                    }
                }
            }
        }
    }

    // ---- block reduction, atomic accumulate ----
#pragma unroll
    for (int off = 16; off > 0; off >>= 1)
        acc += __shfl_xor_sync(0xffffffffu, acc, off);
    if ((tid & 31) == 0) wsum[tid >> 5] = acc;
    __syncthreads();
    if (tid < 32) {
        float v = (tid < BW / 32) ? wsum[tid] : 0.0f;
#pragma unroll
        for (int off = 16; off > 0; off >>= 1)
            v += __shfl_xor_sync(0xffffffffu, v, off);
        if (tid == 0) atomicAdd(&g_acc, (double)v);
    }
}

extern "C" void kernel_launch(void* const* d_in, const int* in_sizes, int n_in,
                              void* d_out, int out_size) {
    const float* pred = (const float*)d_in[0];
    const float* tgt  = (const float*)d_in[1];
    float* out = (float*)d_out;

    const int npix = in_sizes[0];               // 16*3*512*512
    const int planes = npix / (IMG * IMG);      // 48

    init_acc_kernel<<<1, 1>>>();

    dim3 g(2, IMG / CHR, planes);               // 2 strips x 8 chunks x planes

    // per-K tuned: <K, BW, minBlocksPerSM, CH>  (BW=288: 2x~260 useful = 512)
    stat_stream_kernel<3, BWC, 4, CHR><<<g, BWC>>>(pred, tgt);   // 36 warps/SM
    stat_stream_kernel<5, BWC, 3, CHR><<<g, BWC>>>(pred, tgt);   // 27 warps/SM
    stat_stream_kernel<7, BWC, 2, CHR><<<g, BWC>>>(pred, tgt);   // 18 warps/SM

    const double scale = 1.0 / (12.0 * (double)npix);
    finalize_kernel<<<1, 1>>>(out, scale);
}

// round 14
// speedup vs baseline: 1.3838x; 1.3838x over previous
#include <cuda_runtime.h>
#include <math.h>

typedef unsigned long long ull;

#define IMG 512
#define BW  288     // threads per block = columns per strip
#define CH  64      // output rows per chunk

__device__ double g_acc;

__global__ void init_acc_kernel() { g_acc = 0.0; }

__global__ void finalize_kernel(float* out, double scale) {
    out[0] = (float)(g_acc * scale);
}

// ---- f32x2 packed helpers ----
__device__ __forceinline__ ull pack2(float lo, float hi) {
    ull r;
    asm("mov.b64 %0, {%1, %2};" : "=l"(r) : "f"(lo), "f"(hi));
    return r;
}
__device__ __forceinline__ void unpack2(ull v, float& lo, float& hi) {
    asm("mov.b64 {%0, %1}, %2;" : "=f"(lo), "=f"(hi) : "l"(v));
}
__device__ __forceinline__ void ffma2(ull& d, ull a, ull b) {
    asm("fma.rn.f32x2 %0, %1, %2, %0;" : "+l"(d) : "l"(a), "l"(b));
}
__device__ __forceinline__ ull fma2v(ull a, ull b, ull c) {   // a*b + c
    ull d;
    asm("fma.rn.f32x2 %0, %1, %2, %3;" : "=l"(d) : "l"(a), "l"(b), "l"(c));
    return d;
}
__device__ __forceinline__ ull mul2(ull a, ull b) {
    ull d;
    asm("mul.rn.f32x2 %0, %1, %2;" : "=l"(d) : "l"(a), "l"(b));
    return d;
}

// Streaming register-systolic kernel (R9 structure) with per-pixel power
// precompute: xbuf rows hold packed (x, x^2), xcbuf rows hold (xc^3, xc^4),
// so horizontal convs are 2 FFMA2 per tap with one LDS.128.
// Per row iteration p:
//   publish (x,x^2)[p] and (xc^3,xc^4)[p-R-1]; sync;
//   L1 hconv -> h1,hs2; mean/S2 systolic completes row p-R;
//   xc/powers for row p-R staged for next publish;
//   L2 hconv on row p-R-1; m3/m4 systolic completes row p-2R-1.
template <int K, int MINB>
__global__ __launch_bounds__(BW, MINB)
void stat_stream_kernel(const float* __restrict__ pred,
                        const float* __restrict__ tgt)
{
    constexpr int R    = K / 2;
    constexpr int UWB  = BW - 4 * R;          // useful output columns
    constexpr int U    = R + 2;               // ring depth / inner unroll
    constexpr int NRAW = CH + 4 * R + 1;      // rows streamed per chunk
    constexpr int NITER = ((NRAW + U - 1) / U) * U;

    // pad(4) | xcbuf U*BW | xbuf U*BW | pad(4)   (u128 each)
    __shared__ __align__(16) ulonglong2 sbuf[2 * U * BW + 8];
    __shared__ float wsum[BW / 32];
    ulonglong2* const xcbuf = sbuf + 4;
    ulonglong2* const xbuf  = xcbuf + U * BW;

    const int tid = threadIdx.x;
    const int c0  = blockIdx.y * CH;
    const int col = blockIdx.x * UWB - 2 * R + tid;
    const bool incol = (unsigned)col < (unsigned)IMG;
    const bool uc = (tid >= 2 * R) && (tid < 2 * R + UWB) && incol;
    const size_t plane = (size_t)blockIdx.z * (size_t)(IMG * IMG);

    // normalized 1D gaussian, packed into both f32x2 lanes
    ull gp[K];
    {
        const float sigma = (float)K / 6.0f;
        const float inv2s2 = 1.0f / (2.0f * sigma * sigma);
        float gt[K];
        float s = 0.0f;
#pragma unroll
        for (int j = 0; j < K; ++j) {
            float c = (float)(j - K / 2);
            gt[j] = expf(-c * c * inv2s2);
            s += gt[j];
        }
        float inv = 1.0f / s;
#pragma unroll
        for (int j = 0; j < K; ++j) { float w = gt[j] * inv; gp[j] = pack2(w, w); }
    }
    const ull NEG1 = pack2(-1.0f, -1.0f);

    // zero entire ring (incl. pads) so discarded-lane taps stay finite
    for (int i = tid; i < 2 * U * BW + 8; i += BW) {
        ulonglong2 z; z.x = 0ull; z.y = 0ull;
        sbuf[i] = z;
    }

    // systolic partials (K-1 pending each) + register rings
    ull Am[K - 1], As[K - 1], A3[K - 1], A4[K - 1];
#pragma unroll
    for (int i = 0; i < K - 1; ++i) { Am[i] = 0; As[i] = 0; A3[i] = 0; A4[i] = 0; }
    ull xr[U], i3r[U], i4r[U];
#pragma unroll
    for (int i = 0; i < U; ++i) { xr[i] = 0; i3r[i] = 0; i4r[i] = 0; }

    const int r0 = c0 - 2 * R;
    const float* pp = pred + plane + (long long)r0 * IMG + col;
    const float* pt = tgt  + plane + (long long)r0 * IMG + col;

    // preload x row r0
    ull xv;
    {
        float a = 0.0f, b = 0.0f;
        if (incol && ((unsigned)r0 < (unsigned)IMG)) { a = pp[0]; b = pt[0]; }
        xv = pack2(a, b);
        pp += IMG; pt += IMG;
    }
    ull c3_pend = 0ull, c4_pend = 0ull;
    float acc = 0.0f;

    __syncthreads();   // ring zeroing complete

#pragma unroll 1
    for (int p0 = 0; p0 < NITER; p0 += U) {
#pragma unroll
        for (int u = 0; u < U; ++u) {
            const int p = p0 + u;

            // publish (x, x^2) row p and (xc^3, xc^4) row p-R-1
            {
                ulonglong2 xo; xo.x = xv; xo.y = mul2(xv, xv);
                xbuf[u * BW + tid] = xo;
                ulonglong2 co; co.x = c3_pend; co.y = c4_pend;
                xcbuf[u * BW + tid] = co;
            }

            // prefetch next x row (overlaps barrier + compute)
            ull xv_n;
            {
                int rn = r0 + p + 1;
                float a = 0.0f, b = 0.0f;
                if (incol && ((unsigned)rn < (unsigned)IMG)) { a = pp[0]; b = pt[0]; }
                xv_n = pack2(a, b);
                pp += IMG; pt += IMG;
            }
            __syncthreads();

            // ---- level-1 horizontal convs: h1 = conv(x), hs2 = conv(x^2) ----
            ull h1 = 0ull, hs2 = 0ull;
            {
                const ulonglong2* xb = xbuf + u * BW + (tid - R);
#pragma unroll
                for (int j = 0; j < K; ++j) {
                    ulonglong2 t = xb[j];
                    ffma2(h1,  gp[j], t.x);
                    ffma2(hs2, gp[j], t.y);
                }
            }

            // ---- mean/S2 vertical systolic: completes row m = p-R ----
            ull meanc = Am[0]; ffma2(meanc, gp[K - 1], h1);
            ull S2c   = As[0]; ffma2(S2c,   gp[K - 1], hs2);
#pragma unroll
            for (int i = 0; i < K - 2; ++i) {
                ull a = Am[i + 1]; ffma2(a, gp[K - 2 - i], h1);  Am[i] = a;
                ull b = As[i + 1]; ffma2(b, gp[K - 2 - i], hs2); As[i] = b;
            }
            Am[K - 2] = mul2(gp[0], h1);
            As[K - 2] = mul2(gp[0], hs2);

            // ---- xc + powers for row m (x from register ring) ----
            {
                ull xm = xr[(u + U - R) % U];
                int m = r0 + p - R;
                ull xcv = fma2v(meanc, NEG1, xm);
                ull xc2 = mul2(xcv, xcv);
                ull c3  = mul2(xc2, xcv);
                ull c4  = mul2(xc2, xc2);
                bool mimg = incol && ((unsigned)m < (unsigned)IMG);
                c3_pend = mimg ? c3 : 0ull;
                c4_pend = mimg ? c4 : 0ull;
            }
            xr[u] = xv;

            // ---- features at m: |dmean|+|dvar|, inverse rings for skew/kurt ----
            const int m_idx = p - 3 * R;          // m - c0 (uniform across block)
            if ((unsigned)m_idx < (unsigned)CH) {
                float mp, mt, sp, st;
                unpack2(meanc, mp, mt);
                unpack2(S2c,   sp, st);
                float vp = fmaxf(fmaf(-mp, mp, sp), 1e-8f);
                float vt = fmaxf(fmaf(-mt, mt, st), 1e-8f);
                if (uc) acc += fabsf(mp - mt) + fabsf(vp - vt);
                float sdp = sqrtf(vp), sdt = sqrtf(vt);
                float i3p = __fdividef(1.0f, fmaf(sdp, vp, 1e-8f));  // 1/(sd^3+eps)
                float i3t = __fdividef(1.0f, fmaf(sdt, vt, 1e-8f));
                float i4p = __fdividef(1.0f, fmaf(vp, vp, 1e-8f));   // 1/(var^2+eps)
                float i4t = __fdividef(1.0f, fmaf(vt, vt, 1e-8f));
                i3r[u] = pack2(i3p, i3t);
                i4r[u] = pack2(i4p, i4t);
            }

            // ---- level-2 horizontal convs on (xc^3, xc^4) row p-R-1 ----
            ull hc3 = 0ull, hc4 = 0ull;
            {
                const ulonglong2* cb = xcbuf + u * BW + (tid - R);
#pragma unroll
                for (int j = 0; j < K; ++j) {
                    ulonglong2 s = cb[j];
                    ffma2(hc3, gp[j], s.x);
                    ffma2(hc4, gp[j], s.y);
                }
            }

            // ---- m3/m4 vertical systolic: completes output row o = p-2R-1 ----
            ull m3c = A3[0]; ffma2(m3c, gp[K - 1], hc3);
            ull m4c = A4[0]; ffma2(m4c, gp[K - 1], hc4);
#pragma unroll
            for (int i = 0; i < K - 2; ++i) {
                ull a = A3[i + 1]; ffma2(a, gp[K - 2 - i], hc3); A3[i] = a;
                ull b = A4[i + 1]; ffma2(b, gp[K - 2 - i], hc4); A4[i] = b;
            }
            A3[K - 2] = mul2(gp[0], hc3);
            A4[K - 2] = mul2(gp[0], hc4);

            const int o_idx = p - (4 * R + 1);    // o - c0 (uniform)
            if (((unsigned)o_idx < (unsigned)CH) && uc) {
                float m3p, m3t, m4p, m4t;
                unpack2(m3c, m3p, m3t);
                unpack2(m4c, m4p, m4t);
                float i3p, i3t, i4p, i4t;
                unpack2(i3r[(u + 2 * U - (R + 1)) % U], i3p, i3t);
                unpack2(i4r[(u + 2 * U - (R + 1)) % U], i4p, i4t);
                acc += 0.5f   * fabsf(m3p * i3p - m3t * i3t)
                     + 0.001f * fabsf(m4p * i4p - m4t * i4t);
            }

            xv = xv_n;
        }
    }

    // ---- block reduction, atomic accumulate ----
#pragma unroll
    for (int off = 16; off > 0; off >>= 1)
        acc += __shfl_xor_sync(0xffffffffu, acc, off);
    if ((tid & 31) == 0) wsum[tid >> 5] = acc;
    __syncthreads();
    if (tid < 32) {
        float v = (tid < BW / 32) ? wsum[tid] : 0.0f;
#pragma unroll
        for (int off = 16; off > 0; off >>= 1)
            v += __shfl_xor_sync(0xffffffffu, v, off);
        if (tid == 0) atomicAdd(&g_acc, (double)v);
    }
}

extern "C" void kernel_launch(void* const* d_in, const int* in_sizes, int n_in,
                              void* d_out, int out_size) {
    const float* pred = (const float*)d_in[0];
    const float* tgt  = (const float*)d_in[1];
    float* out = (float*)d_out;

    const int npix = in_sizes[0];               // 16*3*512*512
    const int planes = npix / (IMG * IMG);      // 48

    dim3 grid(2, IMG / CH, planes);             // 2 col strips x 8 chunks x planes

    init_acc_kernel<<<1, 1>>>();
    stat_stream_kernel<3, 3><<<grid, BW>>>(pred, tgt);
    stat_stream_kernel<5, 2><<<grid, BW>>>(pred, tgt);
    stat_stream_kernel<7, 2><<<grid, BW>>>(pred, tgt);

    const double scale = 1.0 / (12.0 * (double)npix);
    finalize_kernel<<<1, 1>>>(out, scale);
}

// round 16
// speedup vs baseline: 1.7585x; 1.2707x over previous
#include <cuda_runtime.h>
#include <math.h>

typedef unsigned long long ull;

#define IMG 512
#define BW  192     // threads per block = columns per strip
#define CH  128     // output rows per chunk

__device__ double g_acc;

__global__ void init_acc_kernel() { g_acc = 0.0; }

__global__ void finalize_kernel(float* out, double scale) {
    out[0] = (float)(g_acc * scale);
}

// ---- f32x2 packed helpers ----
__device__ __forceinline__ ull pack2(float lo, float hi) {
    ull r;
    asm("mov.b64 %0, {%1, %2};" : "=l"(r) : "f"(lo), "f"(hi));
    return r;
}
__device__ __forceinline__ void unpack2(ull v, float& lo, float& hi) {
    asm("mov.b64 {%0, %1}, %2;" : "=f"(lo), "=f"(hi) : "l"(v));
}
__device__ __forceinline__ void ffma2(ull& d, ull a, ull b) {
    asm("fma.rn.f32x2 %0, %1, %2, %0;" : "+l"(d) : "l"(a), "l"(b));
}
__device__ __forceinline__ ull fma2v(ull a, ull b, ull c) {   // a*b + c
    ull d;
    asm("fma.rn.f32x2 %0, %1, %2, %3;" : "=l"(d) : "l"(a), "l"(b), "l"(c));
    return d;
}
__device__ __forceinline__ ull mul2(ull a, ull b) {
    ull d;
    asm("mul.rn.f32x2 %0, %1, %2;" : "=l"(d) : "l"(a), "l"(b));
    return d;
}
__device__ __forceinline__ ull add2(ull a, ull b) {
    ull d;
    asm("add.rn.f32x2 %0, %1, %2;" : "=l"(d) : "l"(a), "l"(b));
    return d;
}

// Streaming register-systolic kernel (R9 structure) at higher occupancy.
// One thread = one column. Per row iteration p (one __syncthreads each):
//   publish x[p], xc[p-R-1], xc2[p-R-1];
//   L1 hconv(x, x^2) -> mean/S2 systolic completes row p-R;
//   stage xc, xc2 for row p-R (own x re-read from xS ring);
//   L2 hconv(xc*xc2, xc2*xc2) row p-R-1 -> m3/m4 systolic completes p-2R-1.
// Register diet: symmetric weights (R+1 packed), no x register ring,
// one packed variance ring with rcp recomputed at output.
template <int K, int MINB>
__global__ __launch_bounds__(BW, MINB)
void stat_stream_kernel(const float* __restrict__ pred,
                        const float* __restrict__ tgt)
{
    constexpr int R    = K / 2;
    constexpr int UWB  = BW - 4 * R;          // useful output columns
    constexpr int U    = R + 2;               // ring depth
    constexpr int NRAW = CH + 4 * R + 1;      // row-iterations per chunk
    constexpr int NITER = ((NRAW + U - 1) / U) * U;

    // pad(4) | xS | cS | c2S | pad(4)   each U*BW u64
    __shared__ __align__(16) ull sbuf[3 * U * BW + 8];
    __shared__ float wsum[BW / 32];
    ull* const xS  = sbuf + 4;
    ull* const cS  = xS + U * BW;
    ull* const c2S = cS + U * BW;

    const int tid = threadIdx.x;
    const int c0  = blockIdx.y * CH;
    const int col = blockIdx.x * UWB - 2 * R + tid;
    const bool incol = (unsigned)col < (unsigned)IMG;
    const bool uc = (tid >= 2 * R) && (tid < 2 * R + UWB) && incol;
    const size_t plane = (size_t)blockIdx.z * (size_t)(IMG * IMG);

    // normalized 1D gaussian: only R+1 distinct (symmetric), packed
    ull gw[R + 1];
    {
        const float sigma = (float)K / 6.0f;
        const float inv2s2 = 1.0f / (2.0f * sigma * sigma);
        float gt[R + 1];
        float s = 0.0f;
#pragma unroll
        for (int j = 0; j <= R; ++j) {
            float c = (float)(j - R);
            gt[j] = expf(-c * c * inv2s2);
            s += (j < R) ? 2.0f * gt[j] : gt[j];
        }
        float inv = 1.0f / s;
#pragma unroll
        for (int j = 0; j <= R; ++j) { float w = gt[j] * inv; gw[j] = pack2(w, w); }
    }
    const ull NEG1 = pack2(-1.0f, -1.0f);

    // zero the ring so halo/unpublished taps are finite zeros
    for (int i = tid; i < 3 * U * BW + 8; i += BW) sbuf[i] = 0ull;

    // systolic partials + packed variance ring
    ull Am[K - 1], As[K - 1], A3[K - 1], A4[K - 1];
#pragma unroll
    for (int i = 0; i < K - 1; ++i) { Am[i] = 0; As[i] = 0; A3[i] = 0; A4[i] = 0; }
    ull vr[U];
#pragma unroll
    for (int i = 0; i < U; ++i) vr[i] = 0;

    const int r0 = c0 - 2 * R;
    const float* pp = pred + plane + (long long)r0 * IMG + col;
    const float* pt = tgt  + plane + (long long)r0 * IMG + col;

    // preload x row r0
    ull xv;
    {
        float a = 0.0f, b = 0.0f;
        if (incol && ((unsigned)r0 < (unsigned)IMG)) { a = pp[0]; b = pt[0]; }
        xv = pack2(a, b);
        pp += IMG; pt += IMG;
    }
    ull xc_pend = 0ull, xc2_pend = 0ull;
    float acc = 0.0f;

    __syncthreads();   // ring zeroing complete

#pragma unroll 1
    for (int p0 = 0; p0 < NITER; p0 += U) {
#pragma unroll
        for (int u = 0; u < U; ++u) {
            const int p = p0 + u;

            // publish x row p and (xc, xc2) row p-R-1
            xS [u * BW + tid] = xv;
            cS [u * BW + tid] = xc_pend;
            c2S[u * BW + tid] = xc2_pend;

            // prefetch next x row (overlaps barrier + compute)
            ull xv_n;
            {
                int rn = r0 + p + 1;
                float a = 0.0f, b = 0.0f;
                if (incol && ((unsigned)rn < (unsigned)IMG)) { a = pp[0]; b = pt[0]; }
                xv_n = pack2(a, b);
                pp += IMG; pt += IMG;
            }
            __syncthreads();

            // ---- level-1 horizontal convs (symmetric pairing, 2 chains) ----
            ull h1, hs2;
            {
                const ull* xb = xS + u * BW + (tid - R);
                ull t[K];
#pragma unroll
                for (int j = 0; j < K; ++j) t[j] = xb[j];
                ull h1a = mul2(gw[R], t[R]);
                ull sa  = mul2(gw[R], mul2(t[R], t[R]));
                ull h1b = 0ull, sb = 0ull;
#pragma unroll
                for (int j = 0; j < R; ++j) {
                    ull ps  = add2(t[j], t[K - 1 - j]);
                    ull ps2 = add2(mul2(t[j], t[j]), mul2(t[K - 1 - j], t[K - 1 - j]));
                    if (j & 1) { ffma2(h1b, gw[j], ps); ffma2(sb, gw[j], ps2); }
                    else       { ffma2(h1a, gw[j], ps); ffma2(sa, gw[j], ps2); }
                }
                h1  = add2(h1a, h1b);
                hs2 = add2(sa, sb);
            }

            // ---- mean/S2 vertical systolic: completes row m = p-R ----
            ull meanc = Am[0]; ffma2(meanc, gw[0], h1);     // tap K-1 -> gw[0]
            ull S2c   = As[0]; ffma2(S2c,   gw[0], hs2);
#pragma unroll
            for (int i = 0; i < K - 2; ++i) {
                const int j = K - 2 - i;              // tap index
                const int w = (j <= R) ? j : (K - 1 - j);
                ull a = Am[i + 1]; ffma2(a, gw[w], h1);  Am[i] = a;
                ull b = As[i + 1]; ffma2(b, gw[w], hs2); As[i] = b;
            }
            Am[K - 2] = mul2(gw[0], h1);                 // tap 0 -> gw[0]
            As[K - 2] = mul2(gw[0], hs2);

            // ---- xc, xc2 for row m (own x from xS ring slot (u+2)%U) ----
            {
                ull xm = xS[((u + 2) % U) * BW + tid];
                int m = r0 + p - R;
                ull xcv = fma2v(meanc, NEG1, xm);
                ull xc2 = mul2(xcv, xcv);
                bool mimg = incol && ((unsigned)m < (unsigned)IMG);
                xc_pend  = mimg ? xcv : 0ull;
                xc2_pend = mimg ? xc2 : 0ull;
            }

            // ---- features at m: |dmean|+|dvar|; variance into ring ----
            const int m_idx = p - 3 * R;              // uniform across block
            if ((unsigned)m_idx < (unsigned)CH) {
                float mp, mt, sp, st;
                unpack2(meanc, mp, mt);
                unpack2(S2c,   sp, st);
                float vp = fmaxf(fmaf(-mp, mp, sp), 1e-8f);
                float vt = fmaxf(fmaf(-mt, mt, st), 1e-8f);
                if (uc) acc += fabsf(mp - mt) + fabsf(vp - vt);
                vr[u] = pack2(vp, vt);
            }

            // ---- level-2 horizontal convs on (xc, xc2) row p-R-1 ----
            ull hc3, hc4;
            {
                const ull* cb  = cS  + u * BW + (tid - R);
                const ull* c2b = c2S + u * BW + (tid - R);
                ull h3a = 0ull, h3b = 0ull, h4a = 0ull, h4b = 0ull;
#pragma unroll
                for (int j = 0; j < K; ++j) {
                    const int w = (j <= R) ? j : (K - 1 - j);
                    ull s  = cb[j];
                    ull s2 = c2b[j];
                    ull c3 = mul2(s, s2);
                    ull c4 = mul2(s2, s2);
                    if (j & 1) { ffma2(h3b, gw[w], c3); ffma2(h4b, gw[w], c4); }
                    else       { ffma2(h3a, gw[w], c3); ffma2(h4a, gw[w], c4); }
                }
                hc3 = add2(h3a, h3b);
                hc4 = add2(h4a, h4b);
            }

            // ---- m3/m4 vertical systolic: completes output row o = p-2R-1 ----
            ull m3c = A3[0]; ffma2(m3c, gw[0], hc3);
            ull m4c = A4[0]; ffma2(m4c, gw[0], hc4);
#pragma unroll
            for (int i = 0; i < K - 2; ++i) {
                const int j = K - 2 - i;
                const int w = (j <= R) ? j : (K - 1 - j);
                ull a = A3[i + 1]; ffma2(a, gw[w], hc3); A3[i] = a;
                ull b = A4[i + 1]; ffma2(b, gw[w], hc4); A4[i] = b;
            }
            A3[K - 2] = mul2(gw[0], hc3);
            A4[K - 2] = mul2(gw[0], hc4);

            const int o_idx = p - (4 * R + 1);        // uniform
            if (((unsigned)o_idx < (unsigned)CH) && uc) {
                float vp, vt;
                unpack2(vr[(u + 1) % U], vp, vt);     // var of row o (lag R+1 = U-1)
                float m3p, m3t, m4p, m4t;
                unpack2(m3c, m3p, m3t);
                unpack2(m4c, m4p, m4t);
                float sdp = sqrtf(vp), sdt = sqrtf(vt);
                float skp = __fdividef(m3p, fmaf(sdp, vp, 1e-8f));
                float skt = __fdividef(m3t, fmaf(sdt, vt, 1e-8f));
                float kup = __fdividef(m4p, fmaf(vp, vp, 1e-8f));
                float kut = __fdividef(m4t, fmaf(vt, vt, 1e-8f));
                acc += 0.5f   * fabsf(skp - skt)
                     + 0.001f * fabsf(kup - kut);
            }

            xv = xv_n;
        }
    }

    // ---- block reduction, atomic accumulate ----
#pragma unroll
    for (int off = 16; off > 0; off >>= 1)
        acc += __shfl_xor_sync(0xffffffffu, acc, off);
    if ((tid & 31) == 0) wsum[tid >> 5] = acc;
    __syncthreads();
    if (tid < 32) {
        float v = (tid < BW / 32) ? wsum[tid] : 0.0f;
#pragma unroll
        for (int off = 16; off > 0; off >>= 1)
            v += __shfl_xor_sync(0xffffffffu, v, off);
        if (tid == 0) atomicAdd(&g_acc, (double)v);
    }
}

extern "C" void kernel_launch(void* const* d_in, const int* in_sizes, int n_in,
                              void* d_out, int out_size) {
    const float* pred = (const float*)d_in[0];
    const float* tgt  = (const float*)d_in[1];
    float* out = (float*)d_out;

    const int npix = in_sizes[0];               // 16*3*512*512
    const int planes = npix / (IMG * IMG);      // 48

    dim3 grid(3, IMG / CH, planes);             // 3 strips x 4 chunks x planes
                                                // = 576 blocks (~1 wave at 4/SM)
    init_acc_kernel<<<1, 1>>>();
    stat_stream_kernel<3, 4><<<grid, BW>>>(pred, tgt);
    stat_stream_kernel<5, 4><<<grid, BW>>>(pred, tgt);
    stat_stream_kernel<7, 4><<<grid, BW>>>(pred, tgt);

    const double scale = 1.0 / (12.0 * (double)npix);
    finalize_kernel<<<1, 1>>>(out, scale);
}

// round 17
// speedup vs baseline: 1.7962x; 1.0214x over previous
#include <cuda_runtime.h>
#include <math.h>

typedef unsigned long long ull;

#define IMG 512
#define BW  192     // threads per block = columns per strip
#define CH  128     // output rows per chunk

__device__ double g_acc;

__global__ void init_acc_kernel() { g_acc = 0.0; }

__global__ void finalize_kernel(float* out, double scale) {
    out[0] = (float)(g_acc * scale);
}

// ---- f32x2 packed helpers ----
__device__ __forceinline__ ull pack2(float lo, float hi) {
    ull r;
    asm("mov.b64 %0, {%1, %2};" : "=l"(r) : "f"(lo), "f"(hi));
    return r;
}
__device__ __forceinline__ void unpack2(ull v, float& lo, float& hi) {
    asm("mov.b64 {%0, %1}, %2;" : "=f"(lo), "=f"(hi) : "l"(v));
}
__device__ __forceinline__ void ffma2(ull& d, ull a, ull b) {
    asm("fma.rn.f32x2 %0, %1, %2, %0;" : "+l"(d) : "l"(a), "l"(b));
}
__device__ __forceinline__ ull fma2v(ull a, ull b, ull c) {   // a*b + c
    ull d;
    asm("fma.rn.f32x2 %0, %1, %2, %3;" : "=l"(d) : "l"(a), "l"(b), "l"(c));
    return d;
}
__device__ __forceinline__ ull mul2(ull a, ull b) {
    ull d;
    asm("mul.rn.f32x2 %0, %1, %2;" : "=l"(d) : "l"(a), "l"(b));
    return d;
}
__device__ __forceinline__ ull add2(ull a, ull b) {
    ull d;
    asm("add.rn.f32x2 %0, %1, %2;" : "=l"(d) : "l"(a), "l"(b));
    return d;
}

// Streaming register-systolic kernel. One thread = one column.
// Per row iteration p (one __syncthreads each):
//   publish x[p] and xc[p-R-1];
//   L1 hconv(x, x^2) -> mean/S2 systolic completes row p-R;
//   stage xc for row p-R (own x re-read from xS ring);
//   L2 hconv on xc row p-R-1 (powers computed per tap) ->
//   m3/m4 systolic completes output row p-2R-1.
// Symmetric weights (R+1 packed), packed variance ring, rcp at output.
template <int K, int MINB>
__global__ __launch_bounds__(BW, MINB)
void stat_stream_kernel(const float* __restrict__ pred,
                        const float* __restrict__ tgt)
{
    constexpr int R    = K / 2;
    constexpr int UWB  = BW - 4 * R;          // useful output columns
    constexpr int U    = R + 2;               // ring depth
    constexpr int NRAW = CH + 4 * R + 1;      // row-iterations per chunk
    constexpr int NITER = ((NRAW + U - 1) / U) * U;

    // pad(4) | xS | cS | pad(4)   each U*BW u64
    __shared__ __align__(16) ull sbuf[2 * U * BW + 8];
    __shared__ float wsum[BW / 32];
    ull* const xS = sbuf + 4;
    ull* const cS = xS + U * BW;

    const int tid = threadIdx.x;
    const int c0  = blockIdx.y * CH;
    const int col = blockIdx.x * UWB - 2 * R + tid;
    const bool incol = (unsigned)col < (unsigned)IMG;
    const bool uc = (tid >= 2 * R) && (tid < 2 * R + UWB) && incol;
    const size_t plane = (size_t)blockIdx.z * (size_t)(IMG * IMG);

    // normalized 1D gaussian: only R+1 distinct (symmetric), packed
    ull gw[R + 1];
    {
        const float sigma = (float)K / 6.0f;
        const float inv2s2 = 1.0f / (2.0f * sigma * sigma);
        float gt[R + 1];
        float s = 0.0f;
#pragma unroll
        for (int j = 0; j <= R; ++j) {
            float c = (float)(j - R);
            gt[j] = expf(-c * c * inv2s2);
            s += (j < R) ? 2.0f * gt[j] : gt[j];
        }
        float inv = 1.0f / s;
#pragma unroll
        for (int j = 0; j <= R; ++j) { float w = gt[j] * inv; gw[j] = pack2(w, w); }
    }
    const ull NEG1 = pack2(-1.0f, -1.0f);

    // zero the ring so halo/unpublished taps are finite zeros
    for (int i = tid; i < 2 * U * BW + 8; i += BW) sbuf[i] = 0ull;

    // systolic partials + packed variance ring
    ull Am[K - 1], As[K - 1], A3[K - 1], A4[K - 1];
#pragma unroll
    for (int i = 0; i < K - 1; ++i) { Am[i] = 0; As[i] = 0; A3[i] = 0; A4[i] = 0; }
    ull vr[U];
#pragma unroll
    for (int i = 0; i < U; ++i) vr[i] = 0;

    const int r0 = c0 - 2 * R;
    const float* pp = pred + plane + (long long)r0 * IMG + col;
    const float* pt = tgt  + plane + (long long)r0 * IMG + col;

    // preload x row r0
    ull xv;
    {
        float a = 0.0f, b = 0.0f;
        if (incol && ((unsigned)r0 < (unsigned)IMG)) { a = pp[0]; b = pt[0]; }
        xv = pack2(a, b);
        pp += IMG; pt += IMG;
    }
    ull xc_pend = 0ull;
    float acc = 0.0f;

    __syncthreads();   // ring zeroing complete

#pragma unroll 1
    for (int p0 = 0; p0 < NITER; p0 += U) {
#pragma unroll
        for (int u = 0; u < U; ++u) {
            const int p = p0 + u;

            // publish x row p and xc row p-R-1
            xS[u * BW + tid] = xv;
            cS[u * BW + tid] = xc_pend;

            // prefetch next x row (overlaps barrier + compute)
            ull xv_n;
            {
                int rn = r0 + p + 1;
                float a = 0.0f, b = 0.0f;
                if (incol && ((unsigned)rn < (unsigned)IMG)) { a = pp[0]; b = pt[0]; }
                xv_n = pack2(a, b);
                pp += IMG; pt += IMG;
            }
            __syncthreads();

            // ---- level-1 horizontal convs (symmetric pairing, 2 chains) ----
            ull h1, hs2;
            {
                const ull* xb = xS + u * BW + (tid - R);
                ull t[K];
#pragma unroll
                for (int j = 0; j < K; ++j) t[j] = xb[j];
                ull h1a = mul2(gw[R], t[R]);
                ull sa  = mul2(gw[R], mul2(t[R], t[R]));
                ull h1b = 0ull, sb = 0ull;
#pragma unroll
                for (int j = 0; j < R; ++j) {
                    ull ps  = add2(t[j], t[K - 1 - j]);
                    ull ps2 = add2(mul2(t[j], t[j]), mul2(t[K - 1 - j], t[K - 1 - j]));
                    if (j & 1) { ffma2(h1b, gw[j], ps); ffma2(sb, gw[j], ps2); }
                    else       { ffma2(h1a, gw[j], ps); ffma2(sa, gw[j], ps2); }
                }
                h1  = add2(h1a, h1b);
                hs2 = add2(sa, sb);
            }

            // ---- mean/S2 vertical systolic: completes row m = p-R ----
            ull meanc = Am[0]; ffma2(meanc, gw[0], h1);     // tap K-1 -> gw[0]
            ull S2c   = As[0]; ffma2(S2c,   gw[0], hs2);
#pragma unroll
            for (int i = 0; i < K - 2; ++i) {
                const int j = K - 2 - i;              // tap index
                const int w = (j <= R) ? j : (K - 1 - j);
                ull a = Am[i + 1]; ffma2(a, gw[w], h1);  Am[i] = a;
                ull b = As[i + 1]; ffma2(b, gw[w], hs2); As[i] = b;
            }
            Am[K - 2] = mul2(gw[0], h1);                 // tap 0 -> gw[0]
            As[K - 2] = mul2(gw[0], hs2);

            // ---- xc for row m (own x from xS ring slot (u+2)%U) ----
            {
                ull xm = xS[((u + 2) % U) * BW + tid];
                int m = r0 + p - R;
                ull xcv = fma2v(meanc, NEG1, xm);
                bool mimg = incol && ((unsigned)m < (unsigned)IMG);
                xc_pend = mimg ? xcv : 0ull;
            }

            // ---- features at m: |dmean|+|dvar|; variance into ring ----
            const int m_idx = p - 3 * R;              // uniform across block
            if ((unsigned)m_idx < (unsigned)CH) {
                float mp, mt, sp, st;
                unpack2(meanc, mp, mt);
                unpack2(S2c,   sp, st);
                float vp = fmaxf(fmaf(-mp, mp, sp), 1e-8f);
                float vt = fmaxf(fmaf(-mt, mt, st), 1e-8f);
                if (uc) acc += fabsf(mp - mt) + fabsf(vp - vt);
                vr[u] = pack2(vp, vt);
            }

            // ---- level-2 horizontal convs on xc row p-R-1 (powers per tap) ----
            ull hc3, hc4;
            {
                const ull* cb = cS + u * BW + (tid - R);
                ull h3a = 0ull, h3b = 0ull, h4a = 0ull, h4b = 0ull;
#pragma unroll
                for (int j = 0; j < K; ++j) {
                    const int w = (j <= R) ? j : (K - 1 - j);
                    ull s  = cb[j];
                    ull s2 = mul2(s, s);
                    ull c3 = mul2(s2, s);
                    ull c4 = mul2(s2, s2);
                    if (j & 1) { ffma2(h3b, gw[w], c3); ffma2(h4b, gw[w], c4); }
                    else       { ffma2(h3a, gw[w], c3); ffma2(h4a, gw[w], c4); }
                }
                hc3 = add2(h3a, h3b);
                hc4 = add2(h4a, h4b);
            }

            // ---- m3/m4 vertical systolic: completes output row o = p-2R-1 ----
            ull m3c = A3[0]; ffma2(m3c, gw[0], hc3);
            ull m4c = A4[0]; ffma2(m4c, gw[0], hc4);
#pragma unroll
            for (int i = 0; i < K - 2; ++i) {
                const int j = K - 2 - i;
                const int w = (j <= R) ? j : (K - 1 - j);
                ull a = A3[i + 1]; ffma2(a, gw[w], hc3); A3[i] = a;
                ull b = A4[i + 1]; ffma2(b, gw[w], hc4); A4[i] = b;
            }
            A3[K - 2] = mul2(gw[0], hc3);
            A4[K - 2] = mul2(gw[0], hc4);

            const int o_idx = p - (4 * R + 1);        // uniform
            if (((unsigned)o_idx < (unsigned)CH) && uc) {
                float vp, vt;
                unpack2(vr[(u + 1) % U], vp, vt);     // var of row o (lag R+1 = U-1)
                float m3p, m3t, m4p, m4t;
                unpack2(m3c, m3p, m3t);
                unpack2(m4c, m4p, m4t);
                float sdp = sqrtf(vp), sdt = sqrtf(vt);
                float skp = __fdividef(m3p, fmaf(sdp, vp, 1e-8f));
                float skt = __fdividef(m3t, fmaf(sdt, vt, 1e-8f));
                float kup = __fdividef(m4p, fmaf(vp, vp, 1e-8f));
                float kut = __fdividef(m4t, fmaf(vt, vt, 1e-8f));
                acc += 0.5f   * fabsf(skp - skt)
                     + 0.001f * fabsf(kup - kut);
            }

            xv = xv_n;
        }
    }

    // ---- block reduction, atomic accumulate ----
#pragma unroll
    for (int off = 16; off > 0; off >>= 1)
        acc += __shfl_xor_sync(0xffffffffu, acc, off);
    if ((tid & 31) == 0) wsum[tid >> 5] = acc;
    __syncthreads();
    if (tid < 32) {
        float v = (tid < BW / 32) ? wsum[tid] : 0.0f;
#pragma unroll
        for (int off = 16; off > 0; off >>= 1)
            v += __shfl_xor_sync(0xffffffffu, v, off);
        if (tid == 0) atomicAdd(&g_acc, (double)v);
    }
}

extern "C" void kernel_launch(void* const* d_in, const int* in_sizes, int n_in,
                              void* d_out, int out_size) {
    const float* pred = (const float*)d_in[0];
    const float* tgt  = (const float*)d_in[1];
    float* out = (float*)d_out;

    const int npix = in_sizes[0];               // 16*3*512*512
    const int planes = npix / (IMG * IMG);      // 48

    dim3 grid(3, IMG / CH, planes);             // 3 strips x 4 chunks x planes
                                                // = 576 blocks (~1 wave at 4/SM)
    init_acc_kernel<<<1, 1>>>();
    stat_stream_kernel<3, 4><<<grid, BW>>>(pred, tgt);
    stat_stream_kernel<5, 4><<<grid, BW>>>(pred, tgt);
    stat_stream_kernel<7, 4><<<grid, BW>>>(pred, tgt);

    const double scale = 1.0 / (12.0 * (double)npix);
    finalize_kernel<<<1, 1>>>(out, scale);
}